// round 12
// baseline (speedup 1.0000x reference)
#include <cuda_runtime.h>
#include <cuda_fp16.h>
#include <cstdint>

#define BB 2
#define TT 8192
#define DD 1024
#define MM (BB*TT)
#define PCH 256          // chunks per batch
#define TCH (TT/PCH)     // 32

// ----------------------------- device scratch ------------------------------
__device__ __align__(128) __half g_Xh[(size_t)MM*DD];
__device__ __align__(128) __half g_Wvh[DD*DD];
__device__ __align__(128) __half g_Woh[DD*DD];
__device__ __align__(128) __half g_V[(size_t)MM*DD];
__device__ __align__(128) float2 g_part[(size_t)BB*PCH*DD];
__device__ __align__(128) __half g_Rh[(size_t)MM*DD];

// ------------------------------ PTX helpers --------------------------------
__device__ __forceinline__ uint32_t smem_to_u32(const void* p) {
    uint32_t a;
    asm("{ .reg .u64 t; cvta.to.shared.u64 t, %1; cvt.u32.u64 %0, t; }" : "=r"(a) : "l"(p));
    return a;
}
#define SWZ(o) ((uint32_t)(o) ^ ((((uint32_t)(o)) >> 3) & 0x70))

#define CP_ASYNC16(dst, src) \
    asm volatile("cp.async.cg.shared.global [%0], [%1], 16;" :: "r"(dst), "l"(src))
#define CP_COMMIT() asm volatile("cp.async.commit_group;" ::: "memory")
#define CP_WAIT1() asm volatile("cp.async.wait_group 1;" ::: "memory")
#define CP_WAIT0() asm volatile("cp.async.wait_group 0;" ::: "memory")

#define LDMX4(r0, r1, r2, r3, addr) \
    asm volatile("ldmatrix.sync.aligned.m8n8.x4.shared.b16 {%0,%1,%2,%3}, [%4];" \
        : "=r"(r0), "=r"(r1), "=r"(r2), "=r"(r3) : "r"(addr))

#define MMA16816(d, a, b) \
    asm volatile("mma.sync.aligned.m16n8k16.row.col.f32.f16.f16.f32 " \
        "{%0,%1,%2,%3}, {%4,%5,%6,%7}, {%8,%9}, {%0,%1,%2,%3};" \
        : "+f"((d)[0]), "+f"((d)[1]), "+f"((d)[2]), "+f"((d)[3]) \
        : "r"((a)[0]), "r"((a)[1]), "r"((a)[2]), "r"((a)[3]), \
          "r"((b)[0]), "r"((b)[1]))

// ph = fl32(t*f) (reference rounding), 3-term fp32 Cody-Waite reduction
// (q<=8192 13-bit, H 6-bit mantissa -> q*H exact), MUFU sin/cos on |r|<=pi.
__device__ __forceinline__ void rot_sincos(float ph, float* s, float* c) {
    constexpr double TP = 6.283185307179586;
    constexpr float H = 6.28125f;
    constexpr float Mv = (float)(TP - (double)H);
    constexpr float L  = (float)(TP - (double)H - (double)Mv);
    float q = rintf(ph * 0.15915494309189535f);
    float r = fmaf(q, -H, ph);
    r = fmaf(q, -Mv, r);
    r = fmaf(q, -L, r);
    *s = __sinf(r); *c = __cosf(r);
}

// ------------------------------- split -------------------------------------
__global__ void k_split_x(const float* __restrict__ in) {
    size_t n4 = ((size_t)MM * DD) >> 2;
    const float4* in4 = (const float4*)in;
    __half2* h2 = (__half2*)g_Xh;
    for (size_t i = (size_t)blockIdx.x * blockDim.x + threadIdx.x; i < n4;
         i += (size_t)gridDim.x * blockDim.x) {
        float4 v = in4[i];
        __half2 a, b;
        a.x = __float2half(v.x); a.y = __float2half(v.y);
        b.x = __float2half(v.z); b.y = __float2half(v.w);
        h2[2*i] = a; h2[2*i+1] = b;
    }
}

__global__ void k_split_w(const float* __restrict__ Wv, const float* __restrict__ Wo) {
    size_t n4 = ((size_t)DD * DD) >> 2;
    int half = (blockIdx.x >= 128);
    const float4* in4 = (const float4*)(half ? Wo : Wv);
    __half2* h2 = (__half2*)(half ? g_Woh : g_Wvh);
    int bid = blockIdx.x & 127;
    for (size_t i = (size_t)bid * blockDim.x + threadIdx.x; i < n4;
         i += (size_t)128 * blockDim.x) {
        float4 v = in4[i];
        __half2 a, b;
        a.x = __float2half(v.x); a.y = __float2half(v.y);
        b.x = __float2half(v.z); b.y = __float2half(v.w);
        h2[2*i] = a; h2[2*i+1] = b;
    }
}

// -------------------------------- GEMM -------------------------------------
// Per-batch half GEMM: C[m,n] = sum_k A[b,m,k]*B[n,k], fp16 -> fp32 acc.
// R6 core. which==0 additionally computes pass1's chunk partials in the
// epilogue (each warp's 32 accumulator rows are exactly one 32-t scan chunk).
#define TILEB 16384          // 128 rows x 128B
#define B_BASE 32768
#define GSMEM 65536
#define NCHUNK 16

__global__ void __launch_bounds__(256, 2)
k_gemm(int which, int b, float* __restrict__ outC, const float* __restrict__ freqs) {
    extern __shared__ __align__(1024) char smem[];
    const __half *Ab, *Bw;
    if (which == 0) { Ab = g_Xh; Bw = g_Wvh; }
    else            { Ab = g_Rh; Bw = g_Woh; }
    const __half* Ah = Ab + (size_t)b * TT * DD;

    const uint32_t sb = smem_to_u32(smem);
    const int tid = threadIdx.x, wid = tid >> 5, lid = tid & 31;
    const int warp_m = wid & 3, warp_n = wid >> 2;
    const int tn = blockIdx.x * 128, tm = blockIdx.y * 128;   // tm local to batch

    float acc[2][8][4];
    #pragma unroll
    for (int mi = 0; mi < 2; ++mi)
        #pragma unroll
        for (int ni = 0; ni < 8; ++ni)
            #pragma unroll
            for (int q = 0; q < 4; ++q) acc[mi][ni][q] = 0.f;

    auto load_chunk = [&](int c, int buf) {
        const int k0 = c << 6;
        const char* srcA = (const char*)(Ah + (size_t)tm * DD + k0);
        const char* srcB = (const char*)(Bw + (size_t)tn * DD + k0);
        const uint32_t dA = sb + buf * TILEB;
        const uint32_t dB = sb + B_BASE + buf * TILEB;
        #pragma unroll
        for (int i = 0; i < 4; ++i) {
            int j = tid + i * 256;
            int row = j >> 3, seg = j & 7;
            uint32_t off = SWZ((row << 7) | (seg << 4));
            size_t goff = (size_t)row * (DD * 2) + seg * 16;
            CP_ASYNC16(dA + off, srcA + goff);
            CP_ASYNC16(dB + off, srcB + goff);
        }
        CP_COMMIT();
    };

    load_chunk(0, 0);

    const int a_row = warp_m * 32 + (lid & 7) + ((lid >> 3) & 1) * 8;
    const int a_kof = ((lid >> 4) & 1) * 8;
    const int b_row = warp_n * 64 + (lid & 7) + ((lid >> 4) & 1) * 8;
    const int b_kof = ((lid >> 3) & 1) * 8;

    for (int c = 0; c < NCHUNK; ++c) {
        if (c + 1 < NCHUNK) { load_chunk(c + 1, (c + 1) & 1); CP_WAIT1(); }
        else                { CP_WAIT0(); }
        __syncthreads();

        const uint32_t aB = sb + (c & 1) * TILEB;
        const uint32_t bB = sb + B_BASE + (c & 1) * TILEB;
        #pragma unroll
        for (int kk = 0; kk < 4; ++kk) {
            uint32_t af[2][4], bf[8][2];
            #pragma unroll
            for (int mi = 0; mi < 2; ++mi) {
                uint32_t addr = aB + SWZ(((a_row + mi * 16) << 7) | ((a_kof + kk * 16) << 1));
                LDMX4(af[mi][0], af[mi][1], af[mi][2], af[mi][3], addr);
            }
            #pragma unroll
            for (int ni = 0; ni < 4; ++ni) {
                uint32_t r0, r1, r2, r3;
                uint32_t addr = bB + SWZ(((b_row + ni * 16) << 7) | ((b_kof + kk * 16) << 1));
                LDMX4(r0, r1, r2, r3, addr);
                bf[2*ni][0] = r0; bf[2*ni][1] = r1;
                bf[2*ni+1][0] = r2; bf[2*ni+1][1] = r3;
            }
            #pragma unroll
            for (int mi = 0; mi < 2; ++mi)
                #pragma unroll
                for (int ni = 0; ni < 8; ++ni)
                    MMA16816(acc[mi][ni], af[mi], bf[ni]);
        }
        __syncthreads();
    }

    if (which == 0) {
        // ---- V (fp16) stores ----
        #pragma unroll
        for (int mi = 0; mi < 2; ++mi) {
            int m = tm + warp_m * 32 + mi * 16 + (lid >> 2);
            int n0 = tn + warp_n * 64 + (lid & 3) * 2;
            __half* r0p = g_V + ((size_t)b * TT + m) * DD + n0;
            __half* r1p = g_V + ((size_t)b * TT + m + 8) * DD + n0;
            #pragma unroll
            for (int ni = 0; ni < 8; ++ni) {
                __half2 v0, v1;
                v0.x = __float2half(acc[mi][ni][0]); v0.y = __float2half(acc[mi][ni][1]);
                v1.x = __float2half(acc[mi][ni][2]); v1.y = __float2half(acc[mi][ni][3]);
                *(__half2*)(r0p + ni * 8) = v0;
                *(__half2*)(r1p + ni * 8) = v1;
            }
        }
        // ---- fused pass1: per-warp chunk partial ----
        const int t_base = tm + warp_m * 32;
        const int ch = t_base >> 5;
        const int dbase = tn + warp_n * 64 + (lid & 3) * 2;
        #pragma unroll
        for (int nh = 0; nh < 2; ++nh) {
            float fr[8], pre[8], pim[8];
            #pragma unroll
            for (int nj = 0; nj < 4; ++nj) {
                int d = dbase + (nh * 4 + nj) * 8;
                fr[2*nj]   = freqs[d];
                fr[2*nj+1] = freqs[d + 1];
                pre[2*nj] = 0.f; pim[2*nj] = 0.f;
                pre[2*nj+1] = 0.f; pim[2*nj+1] = 0.f;
            }
            #pragma unroll
            for (int mi = 0; mi < 2; ++mi)
                #pragma unroll
                for (int h = 0; h < 2; ++h) {
                    float t_f = (float)(t_base + mi * 16 + (lid >> 2) + h * 8);
                    #pragma unroll
                    for (int nj = 0; nj < 4; ++nj) {
                        int ni = nh * 4 + nj;
                        #pragma unroll
                        for (int e = 0; e < 2; ++e) {
                            int j = 2 * nj + e;
                            float s, c; rot_sincos(t_f * fr[j], &s, &c);
                            float v = acc[mi][ni][h * 2 + e];
                            pre[j] += v * c; pim[j] += v * s;
                        }
                    }
                }
            #pragma unroll
            for (int j = 0; j < 8; ++j) {
                #pragma unroll
                for (int off = 4; off < 32; off <<= 1) {
                    pre[j] += __shfl_xor_sync(0xFFFFFFFFu, pre[j], off);
                    pim[j] += __shfl_xor_sync(0xFFFFFFFFu, pim[j], off);
                }
            }
            if (lid < 4) {
                #pragma unroll
                for (int nj = 0; nj < 4; ++nj) {
                    int d = dbase + (nh * 4 + nj) * 8;
                    float4 w = make_float4(pre[2*nj], pim[2*nj], pre[2*nj+1], pim[2*nj+1]);
                    *(float4*)&g_part[((size_t)b * PCH + ch) * DD + d] = w;
                }
            }
        }
    } else {
        #pragma unroll
        for (int mi = 0; mi < 2; ++mi) {
            int m = tm + warp_m * 32 + mi * 16 + (lid >> 2);
            int n0 = tn + warp_n * 64 + (lid & 3) * 2;
            float* r0p = outC + ((size_t)b * TT + m) * DD + n0;
            float* r1p = outC + ((size_t)b * TT + m + 8) * DD + n0;
            #pragma unroll
            for (int ni = 0; ni < 8; ++ni) {
                *(float2*)(r0p + ni * 8) = make_float2(acc[mi][ni][0], acc[mi][ni][1]);
                *(float2*)(r1p + ni * 8) = make_float2(acc[mi][ni][2], acc[mi][ni][3]);
            }
        }
    }
}

// ------------------------------- scan --------------------------------------
// pass2 (per batch): one WARP per d scan of 256 chunk partials. Lane owns 8
// chunks: load 8 (MLP=8), in-lane exclusive scan, shfl_up scan of lane totals.
__global__ void k_pass2(int b) {
    int gw = (blockIdx.x * blockDim.x + threadIdx.x) >> 5;   // 0..1023 = d
    int lid = threadIdx.x & 31;
    size_t base = (size_t)b * PCH * DD + gw;
    float2 v[8];
    #pragma unroll
    for (int u = 0; u < 8; ++u)
        v[u] = g_part[base + (size_t)(lid * 8 + u) * DD];
    float2 run = make_float2(0.f, 0.f);
    #pragma unroll
    for (int u = 0; u < 8; ++u) {
        float2 tv = v[u];
        v[u] = run;
        run.x += tv.x; run.y += tv.y;
    }
    float sx = run.x, sy = run.y;
    #pragma unroll
    for (int off = 1; off < 32; off <<= 1) {
        float tx = __shfl_up_sync(0xFFFFFFFFu, sx, off);
        float ty = __shfl_up_sync(0xFFFFFFFFu, sy, off);
        if (lid >= off) { sx += tx; sy += ty; }
    }
    float ox = sx - run.x, oy = sy - run.y;   // exclusive lane offset
    #pragma unroll
    for (int u = 0; u < 8; ++u)
        g_part[base + (size_t)(lid * 8 + u) * DD] = make_float2(v[u].x + ox, v[u].y + oy);
}

// pass3 (per batch): finish scan within chunk, unbind, write R (fp16).
__global__ void k_pass3(int b, const float* __restrict__ freqs) {
    const int ch = blockIdx.x, tid = threadIdx.x;
    float2 f[2];
    f[0] = *(const float2*)(freqs + 2*tid);
    f[1] = *(const float2*)(freqs + 512 + 2*tid);
    float2 a[2][2];
    #pragma unroll
    for (int jj = 0; jj < 2; ++jj) {
        int d = jj * 512 + 2 * tid;
        *(float4*)&a[jj][0] = *(float4*)&g_part[((size_t)b * PCH + ch) * DD + d];
    }
    size_t base = ((size_t)b * TT + (size_t)ch * TCH) * DD;
    const __half2* vp = (const __half2*)(g_V + base) + tid;
    __half2* rh = (__half2*)(g_Rh + base) + tid;
    for (int tl = 0; tl < TCH; ++tl) {
        float t = (float)(ch * TCH + tl);
        #pragma unroll
        for (int jj = 0; jj < 2; ++jj) {
            float sx, cx, sy, cy;
            rot_sincos(t * f[jj].x, &sx, &cx);
            rot_sincos(t * f[jj].y, &sy, &cy);
            float2 v = __half22float2(vp[jj * 256]);
            a[jj][0].x += v.x * cx; a[jj][0].y += v.x * sx;
            a[jj][1].x += v.y * cy; a[jj][1].y += v.y * sy;
            __half2 r;
            r.x = __float2half(a[jj][0].x * cx + a[jj][0].y * sx);
            r.y = __float2half(a[jj][1].x * cy + a[jj][1].y * sy);
            rh[jj * 256] = r;
        }
        vp += DD / 2; rh += DD / 2;
    }
}

// ------------------------------- launch ------------------------------------
extern "C" void kernel_launch(void* const* d_in, const int* in_sizes, int n_in,
                              void* d_out, int out_size) {
    const float* x     = (const float*)d_in[0];
    const float* Wv    = (const float*)d_in[2];
    const float* Wo    = (const float*)d_in[3];
    const float* freqs = (const float*)d_in[4];
    float* out = (float*)d_out;

    static cudaStream_t s2 = nullptr;
    static cudaEvent_t ev1 = nullptr, evB = nullptr;
    if (!s2) {
        cudaFuncSetAttribute(k_gemm, cudaFuncAttributeMaxDynamicSharedMemorySize, GSMEM);
        cudaStreamCreateWithFlags(&s2, cudaStreamNonBlocking);
        cudaEventCreateWithFlags(&ev1, cudaEventDisableTiming);
        cudaEventCreateWithFlags(&evB, cudaEventDisableTiming);
    }

    // splits (both batches / both weights) on the capture stream
    k_split_x<<<2048, 256>>>(x);
    k_split_w<<<256, 256>>>(Wv, Wo);

    // batch-0 chain on the capture stream
    k_gemm<<<dim3(8, 64), 256, GSMEM>>>(0, 0, nullptr, freqs);   // GEMM1(b0)+pass1
    cudaEventRecord(ev1, 0);                                     // stagger point

    // batch-1 chain on s2 (forked after GEMM1(b0))
    cudaStreamWaitEvent(s2, ev1, 0);
    k_gemm<<<dim3(8, 64), 256, GSMEM, s2>>>(0, 1, nullptr, freqs);
    k_pass2<<<128, 256, 0, s2>>>(1);
    k_pass3<<<PCH, 256, 0, s2>>>(1, freqs);
    k_gemm<<<dim3(8, 64), 256, GSMEM, s2>>>(1, 1, out, freqs);
    cudaEventRecord(evB, s2);

    // continue batch-0 chain (overlaps with s2)
    k_pass2<<<128, 256>>>(0);
    k_pass3<<<PCH, 256>>>(0, freqs);
    k_gemm<<<dim3(8, 64), 256, GSMEM>>>(1, 0, out, freqs);

    // join
    cudaStreamWaitEvent(0, evB, 0);
}

// round 13
// speedup vs baseline: 1.0252x; 1.0252x over previous
#include <cuda_runtime.h>
#include <cuda_fp16.h>
#include <cstdint>

#define BB 2
#define TT 8192
#define DD 1024
#define MM (BB*TT)
#define PCH 256
#define TCH (TT/PCH)     // 32

// ----------------------------- device scratch ------------------------------
__device__ __align__(128) __half g_Xh[(size_t)MM*DD];
__device__ __align__(128) __half g_Wvh[DD*DD];
__device__ __align__(128) __half g_Woh[DD*DD];
__device__ __align__(128) __half g_V[(size_t)MM*DD];
__device__ __align__(128) float2 g_part[(size_t)BB*PCH*DD];
__device__ __align__(128) __half g_Rh[(size_t)MM*DD];

// ------------------------------ PTX helpers --------------------------------
__device__ __forceinline__ uint32_t smem_to_u32(const void* p) {
    uint32_t a;
    asm("{ .reg .u64 t; cvta.to.shared.u64 t, %1; cvt.u32.u64 %0, t; }" : "=r"(a) : "l"(p));
    return a;
}
#define SWZ(o) ((uint32_t)(o) ^ ((((uint32_t)(o)) >> 3) & 0x70))

#define CP_ASYNC16(dst, src) \
    asm volatile("cp.async.cg.shared.global [%0], [%1], 16;" :: "r"(dst), "l"(src))
#define CP_COMMIT() asm volatile("cp.async.commit_group;" ::: "memory")
#define CP_WAIT1() asm volatile("cp.async.wait_group 1;" ::: "memory")
#define CP_WAIT0() asm volatile("cp.async.wait_group 0;" ::: "memory")

#define LDMX4(r0, r1, r2, r3, addr) \
    asm volatile("ldmatrix.sync.aligned.m8n8.x4.shared.b16 {%0,%1,%2,%3}, [%4];" \
        : "=r"(r0), "=r"(r1), "=r"(r2), "=r"(r3) : "r"(addr))

#define MMA16816(d, a, b) \
    asm volatile("mma.sync.aligned.m16n8k16.row.col.f32.f16.f16.f32 " \
        "{%0,%1,%2,%3}, {%4,%5,%6,%7}, {%8,%9}, {%0,%1,%2,%3};" \
        : "+f"((d)[0]), "+f"((d)[1]), "+f"((d)[2]), "+f"((d)[3]) \
        : "r"((a)[0]), "r"((a)[1]), "r"((a)[2]), "r"((a)[3]), \
          "r"((b)[0]), "r"((b)[1]))

// ph = fl32(t*f) (reference rounding), 3-term fp32 Cody-Waite reduction
// (q<=8192 13-bit, H 6-bit mantissa -> q*H exact), MUFU sin/cos on |r|<=pi.
__device__ __forceinline__ void rot_sincos(float ph, float* s, float* c) {
    constexpr double TP = 6.283185307179586;
    constexpr float H = 6.28125f;
    constexpr float Mv = (float)(TP - (double)H);
    constexpr float L  = (float)(TP - (double)H - (double)Mv);
    float q = rintf(ph * 0.15915494309189535f);
    float r = fmaf(q, -H, ph);
    r = fmaf(q, -Mv, r);
    r = fmaf(q, -L, r);
    *s = __sinf(r); *c = __cosf(r);
}

// ------------------------------- split -------------------------------------
// One launch: blocks [0,2048) convert x; [2048,2176) Wv; [2176,2304) Wo.
__global__ void k_split(const float* __restrict__ x,
                        const float* __restrict__ Wv,
                        const float* __restrict__ Wo) {
    const float4* in4;
    __half2* h2;
    size_t n4, i0, stride;
    if (blockIdx.x < 2048) {
        n4 = ((size_t)MM * DD) >> 2;
        in4 = (const float4*)x; h2 = (__half2*)g_Xh;
        i0 = (size_t)blockIdx.x * blockDim.x + threadIdx.x;
        stride = (size_t)2048 * blockDim.x;
    } else {
        n4 = ((size_t)DD * DD) >> 2;
        int half = (blockIdx.x >= 2176);
        in4 = (const float4*)(half ? Wo : Wv);
        h2 = (__half2*)(half ? g_Woh : g_Wvh);
        int bid = (blockIdx.x - 2048) & 127;
        i0 = (size_t)bid * blockDim.x + threadIdx.x;
        stride = (size_t)128 * blockDim.x;
    }
    for (size_t i = i0; i < n4; i += stride) {
        float4 v = in4[i];
        __half2 a, b;
        a.x = __float2half(v.x); a.y = __float2half(v.y);
        b.x = __float2half(v.z); b.y = __float2half(v.w);
        h2[2*i] = a; h2[2*i+1] = b;
    }
}

// -------------------------------- GEMM -------------------------------------
// C[m,n] = sum_k A[m,k]*B[n,k], fp16 x fp16 -> fp32 acc. R6 core.
// which==0 additionally computes pass1's chunk partials in the epilogue
// (each warp's 32 accumulator rows are exactly one 32-t scan chunk).
#define TILEB 16384          // 128 rows x 128B
#define B_BASE 32768
#define GSMEM 65536
#define NCHUNK 16

__global__ void __launch_bounds__(256, 2)
k_gemm(int which, float* __restrict__ outC, const float* __restrict__ freqs) {
    extern __shared__ __align__(1024) char smem[];
    const __half *Ah, *Bh;
    if (which == 0) { Ah = g_Xh; Bh = g_Wvh; }
    else            { Ah = g_Rh; Bh = g_Woh; }

    const uint32_t sb = smem_to_u32(smem);
    const int tid = threadIdx.x, wid = tid >> 5, lid = tid & 31;
    const int warp_m = wid & 3, warp_n = wid >> 2;
    const int tn = blockIdx.x * 128, tm = blockIdx.y * 128;

    float acc[2][8][4];
    #pragma unroll
    for (int mi = 0; mi < 2; ++mi)
        #pragma unroll
        for (int ni = 0; ni < 8; ++ni)
            #pragma unroll
            for (int q = 0; q < 4; ++q) acc[mi][ni][q] = 0.f;

    auto load_chunk = [&](int c, int buf) {
        const int k0 = c << 6;
        const char* srcA = (const char*)(Ah + (size_t)tm * DD + k0);
        const char* srcB = (const char*)(Bh + (size_t)tn * DD + k0);
        const uint32_t dA = sb + buf * TILEB;
        const uint32_t dB = sb + B_BASE + buf * TILEB;
        #pragma unroll
        for (int i = 0; i < 4; ++i) {
            int j = tid + i * 256;
            int row = j >> 3, seg = j & 7;
            uint32_t off = SWZ((row << 7) | (seg << 4));
            size_t goff = (size_t)row * (DD * 2) + seg * 16;
            CP_ASYNC16(dA + off, srcA + goff);
            CP_ASYNC16(dB + off, srcB + goff);
        }
        CP_COMMIT();
    };

    load_chunk(0, 0);

    const int a_row = warp_m * 32 + (lid & 7) + ((lid >> 3) & 1) * 8;
    const int a_kof = ((lid >> 4) & 1) * 8;
    const int b_row = warp_n * 64 + (lid & 7) + ((lid >> 4) & 1) * 8;
    const int b_kof = ((lid >> 3) & 1) * 8;

    for (int c = 0; c < NCHUNK; ++c) {
        if (c + 1 < NCHUNK) { load_chunk(c + 1, (c + 1) & 1); CP_WAIT1(); }
        else                { CP_WAIT0(); }
        __syncthreads();

        const uint32_t aB = sb + (c & 1) * TILEB;
        const uint32_t bB = sb + B_BASE + (c & 1) * TILEB;
        #pragma unroll
        for (int kk = 0; kk < 4; ++kk) {
            uint32_t af[2][4], bf[8][2];
            #pragma unroll
            for (int mi = 0; mi < 2; ++mi) {
                uint32_t addr = aB + SWZ(((a_row + mi * 16) << 7) | ((a_kof + kk * 16) << 1));
                LDMX4(af[mi][0], af[mi][1], af[mi][2], af[mi][3], addr);
            }
            #pragma unroll
            for (int ni = 0; ni < 4; ++ni) {
                uint32_t r0, r1, r2, r3;
                uint32_t addr = bB + SWZ(((b_row + ni * 16) << 7) | ((b_kof + kk * 16) << 1));
                LDMX4(r0, r1, r2, r3, addr);
                bf[2*ni][0] = r0; bf[2*ni][1] = r1;
                bf[2*ni+1][0] = r2; bf[2*ni+1][1] = r3;
            }
            #pragma unroll
            for (int mi = 0; mi < 2; ++mi)
                #pragma unroll
                for (int ni = 0; ni < 8; ++ni)
                    MMA16816(acc[mi][ni], af[mi], bf[ni]);
        }
        __syncthreads();
    }

    if (which == 0) {
        // ---- V (fp16) stores ----
        #pragma unroll
        for (int mi = 0; mi < 2; ++mi) {
            int m = tm + warp_m * 32 + mi * 16 + (lid >> 2);
            int n0 = tn + warp_n * 64 + (lid & 3) * 2;
            __half* r0p = g_V + (size_t)m * DD + n0;
            __half* r1p = g_V + (size_t)(m + 8) * DD + n0;
            #pragma unroll
            for (int ni = 0; ni < 8; ++ni) {
                __half2 v0, v1;
                v0.x = __float2half(acc[mi][ni][0]); v0.y = __float2half(acc[mi][ni][1]);
                v1.x = __float2half(acc[mi][ni][2]); v1.y = __float2half(acc[mi][ni][3]);
                *(__half2*)(r0p + ni * 8) = v0;
                *(__half2*)(r1p + ni * 8) = v1;
            }
        }
        // ---- fused pass1: per-warp chunk partial ----
        const int b = tm >> 13;
        const int t_base = (tm & 8191) + warp_m * 32;
        const int ch = t_base >> 5;
        const int dbase = tn + warp_n * 64 + (lid & 3) * 2;
        #pragma unroll
        for (int nh = 0; nh < 2; ++nh) {
            float fr[8], pre[8], pim[8];
            #pragma unroll
            for (int nj = 0; nj < 4; ++nj) {
                int d = dbase + (nh * 4 + nj) * 8;
                fr[2*nj]   = freqs[d];
                fr[2*nj+1] = freqs[d + 1];
                pre[2*nj] = 0.f; pim[2*nj] = 0.f;
                pre[2*nj+1] = 0.f; pim[2*nj+1] = 0.f;
            }
            #pragma unroll
            for (int mi = 0; mi < 2; ++mi)
                #pragma unroll
                for (int h = 0; h < 2; ++h) {
                    float t_f = (float)(t_base + mi * 16 + (lid >> 2) + h * 8);
                    #pragma unroll
                    for (int nj = 0; nj < 4; ++nj) {
                        int ni = nh * 4 + nj;
                        #pragma unroll
                        for (int e = 0; e < 2; ++e) {
                            int j = 2 * nj + e;
                            float s, c; rot_sincos(t_f * fr[j], &s, &c);
                            float v = acc[mi][ni][h * 2 + e];
                            pre[j] += v * c; pim[j] += v * s;
                        }
                    }
                }
            #pragma unroll
            for (int j = 0; j < 8; ++j) {
                #pragma unroll
                for (int off = 4; off < 32; off <<= 1) {
                    pre[j] += __shfl_xor_sync(0xFFFFFFFFu, pre[j], off);
                    pim[j] += __shfl_xor_sync(0xFFFFFFFFu, pim[j], off);
                }
            }
            if (lid < 4) {
                #pragma unroll
                for (int nj = 0; nj < 4; ++nj) {
                    int d = dbase + (nh * 4 + nj) * 8;
                    float4 w = make_float4(pre[2*nj], pim[2*nj], pre[2*nj+1], pim[2*nj+1]);
                    *(float4*)&g_part[((size_t)b * PCH + ch) * DD + d] = w;
                }
            }
        }
    } else {
        #pragma unroll
        for (int mi = 0; mi < 2; ++mi) {
            int m = tm + warp_m * 32 + mi * 16 + (lid >> 2);
            int n0 = tn + warp_n * 64 + (lid & 3) * 2;
            float* r0p = outC + (size_t)m * DD + n0;
            float* r1p = outC + (size_t)(m + 8) * DD + n0;
            #pragma unroll
            for (int ni = 0; ni < 8; ++ni) {
                *(float2*)(r0p + ni * 8) = make_float2(acc[mi][ni][0], acc[mi][ni][1]);
                *(float2*)(r1p + ni * 8) = make_float2(acc[mi][ni][2], acc[mi][ni][3]);
            }
        }
    }
}

// ------------------------------- scan --------------------------------------
// pass2: one WARP per (b,d) scan of 256 chunk partials. Lane owns 8 chunks:
// load 8 (MLP=8), in-lane exclusive scan, shfl_up scan of lane totals.
__global__ void k_pass2() {
    int gw = (blockIdx.x * blockDim.x + threadIdx.x) >> 5;   // 0..2047
    int lid = threadIdx.x & 31;
    int b = gw >> 10, d = gw & 1023;
    size_t base = (size_t)b * PCH * DD + d;
    float2 v[8];
    #pragma unroll
    for (int u = 0; u < 8; ++u)
        v[u] = g_part[base + (size_t)(lid * 8 + u) * DD];
    float2 run = make_float2(0.f, 0.f);
    #pragma unroll
    for (int u = 0; u < 8; ++u) {
        float2 tv = v[u];
        v[u] = run;
        run.x += tv.x; run.y += tv.y;
    }
    float sx = run.x, sy = run.y;
    #pragma unroll
    for (int off = 1; off < 32; off <<= 1) {
        float tx = __shfl_up_sync(0xFFFFFFFFu, sx, off);
        float ty = __shfl_up_sync(0xFFFFFFFFu, sy, off);
        if (lid >= off) { sx += tx; sy += ty; }
    }
    float ox = sx - run.x, oy = sy - run.y;   // exclusive lane offset
    #pragma unroll
    for (int u = 0; u < 8; ++u)
        g_part[base + (size_t)(lid * 8 + u) * DD] = make_float2(v[u].x + ox, v[u].y + oy);
}

// pass3: finish scan within chunk, unbind, write R (fp16). Both batches in
// one block -> each rotor evaluation shared.
__global__ void k_pass3(const float* __restrict__ freqs) {
    const int ch = blockIdx.x, tid = threadIdx.x;
    float2 f[2];
    f[0] = *(const float2*)(freqs + 2*tid);
    f[1] = *(const float2*)(freqs + 512 + 2*tid);
    float2 a0[2][2], a1[2][2];
    #pragma unroll
    for (int jj = 0; jj < 2; ++jj) {
        int d = jj * 512 + 2 * tid;
        *(float4*)&a0[jj][0] = *(float4*)&g_part[(size_t)ch * DD + d];
        *(float4*)&a1[jj][0] = *(float4*)&g_part[(size_t)(PCH + ch) * DD + d];
    }
    const __half2* vp0 = (const __half2*)(g_V + (size_t)ch * TCH * DD) + tid;
    const __half2* vp1 = vp0 + (size_t)TT * DD / 2;
    __half2* rh0 = (__half2*)(g_Rh + (size_t)ch * TCH * DD) + tid;
    __half2* rh1 = rh0 + (size_t)TT * DD / 2;
    for (int tl = 0; tl < TCH; ++tl) {
        float t = (float)(ch * TCH + tl);
        #pragma unroll
        for (int jj = 0; jj < 2; ++jj) {
            float sx, cx, sy, cy;
            rot_sincos(t * f[jj].x, &sx, &cx);
            rot_sincos(t * f[jj].y, &sy, &cy);
            float2 v0 = __half22float2(vp0[jj * 256]);
            float2 v1 = __half22float2(vp1[jj * 256]);
            a0[jj][0].x += v0.x * cx; a0[jj][0].y += v0.x * sx;
            a0[jj][1].x += v0.y * cy; a0[jj][1].y += v0.y * sy;
            a1[jj][0].x += v1.x * cx; a1[jj][0].y += v1.x * sx;
            a1[jj][1].x += v1.y * cy; a1[jj][1].y += v1.y * sy;
            __half2 r0, r1;
            r0.x = __float2half(a0[jj][0].x * cx + a0[jj][0].y * sx);
            r0.y = __float2half(a0[jj][1].x * cy + a0[jj][1].y * sy);
            r1.x = __float2half(a1[jj][0].x * cx + a1[jj][0].y * sx);
            r1.y = __float2half(a1[jj][1].x * cy + a1[jj][1].y * sy);
            rh0[jj * 256] = r0;
            rh1[jj * 256] = r1;
        }
        vp0 += DD / 2; vp1 += DD / 2; rh0 += DD / 2; rh1 += DD / 2;
    }
}

// ------------------------------- launch ------------------------------------
extern "C" void kernel_launch(void* const* d_in, const int* in_sizes, int n_in,
                              void* d_out, int out_size) {
    const float* x     = (const float*)d_in[0];
    const float* Wv    = (const float*)d_in[2];
    const float* Wo    = (const float*)d_in[3];
    const float* freqs = (const float*)d_in[4];
    float* out = (float*)d_out;

    static int smem_set = 0;
    if (!smem_set) {
        cudaFuncSetAttribute(k_gemm, cudaFuncAttributeMaxDynamicSharedMemorySize, GSMEM);
        smem_set = 1;
    }

    k_split<<<2304, 256>>>(x, Wv, Wo);

    k_gemm<<<dim3(8, 128), 256, GSMEM>>>(0, nullptr, freqs);   // GEMM1 + fused pass1

    k_pass2<<<512, 128>>>();
    k_pass3<<<PCH, 256>>>(freqs);

    k_gemm<<<dim3(8, 128), 256, GSMEM>>>(1, out, freqs);
}

// round 14
// speedup vs baseline: 1.0937x; 1.0668x over previous
#include <cuda_runtime.h>
#include <cuda_fp16.h>
#include <cstdint>

#define BB 2
#define TT 8192
#define DD 1024
#define MM (BB*TT)
#define PCH 256
#define TCH (TT/PCH)     // 32

// ----------------------------- device scratch ------------------------------
__device__ __align__(128) __half g_Xh[(size_t)MM*DD];
__device__ __align__(128) __half g_Wvh[DD*DD];
__device__ __align__(128) __half g_Woh[DD*DD];
__device__ __align__(128) __half g_V[(size_t)MM*DD];
__device__ __align__(128) float2 g_part[(size_t)BB*PCH*DD];
__device__ __align__(128) __half g_Rh[(size_t)MM*DD];

// ------------------------------ PTX helpers --------------------------------
__device__ __forceinline__ uint32_t smem_to_u32(const void* p) {
    uint32_t a;
    asm("{ .reg .u64 t; cvta.to.shared.u64 t, %1; cvt.u32.u64 %0, t; }" : "=r"(a) : "l"(p));
    return a;
}
#define SWZ(o) ((uint32_t)(o) ^ ((((uint32_t)(o)) >> 3) & 0x70))

#define CP_ASYNC16(dst, src) \
    asm volatile("cp.async.cg.shared.global [%0], [%1], 16;" :: "r"(dst), "l"(src))
#define CP_COMMIT() asm volatile("cp.async.commit_group;" ::: "memory")
#define CP_WAIT1() asm volatile("cp.async.wait_group 1;" ::: "memory")
#define CP_WAIT0() asm volatile("cp.async.wait_group 0;" ::: "memory")

#define LDMX4(r0, r1, r2, r3, addr) \
    asm volatile("ldmatrix.sync.aligned.m8n8.x4.shared.b16 {%0,%1,%2,%3}, [%4];" \
        : "=r"(r0), "=r"(r1), "=r"(r2), "=r"(r3) : "r"(addr))

#define MMA16816(d, a, b) \
    asm volatile("mma.sync.aligned.m16n8k16.row.col.f32.f16.f16.f32 " \
        "{%0,%1,%2,%3}, {%4,%5,%6,%7}, {%8,%9}, {%0,%1,%2,%3};" \
        : "+f"((d)[0]), "+f"((d)[1]), "+f"((d)[2]), "+f"((d)[3]) \
        : "r"((a)[0]), "r"((a)[1]), "r"((a)[2]), "r"((a)[3]), \
          "r"((b)[0]), "r"((b)[1]))

// ph = fl32(t*f) (reference rounding), 3-term fp32 Cody-Waite reduction
// (q<=8192 13-bit, H 6-bit mantissa -> q*H exact), MUFU sin/cos on |r|<=pi.
__device__ __forceinline__ void rot_sincos(float ph, float* s, float* c) {
    constexpr double TP = 6.283185307179586;
    constexpr float H = 6.28125f;
    constexpr float Mv = (float)(TP - (double)H);
    constexpr float L  = (float)(TP - (double)H - (double)Mv);
    float q = rintf(ph * 0.15915494309189535f);
    float r = fmaf(q, -H, ph);
    r = fmaf(q, -Mv, r);
    r = fmaf(q, -L, r);
    *s = __sinf(r); *c = __cosf(r);
}

// ------------------------------- split -------------------------------------
// One launch: blocks [0,2048) convert x; [2048,2176) Wv; [2176,2304) Wo.
__global__ void k_split(const float* __restrict__ x,
                        const float* __restrict__ Wv,
                        const float* __restrict__ Wo) {
    const float4* in4;
    __half2* h2;
    size_t n4, i0, stride;
    if (blockIdx.x < 2048) {
        n4 = ((size_t)MM * DD) >> 2;
        in4 = (const float4*)x; h2 = (__half2*)g_Xh;
        i0 = (size_t)blockIdx.x * blockDim.x + threadIdx.x;
        stride = (size_t)2048 * blockDim.x;
    } else {
        n4 = ((size_t)DD * DD) >> 2;
        int half = (blockIdx.x >= 2176);
        in4 = (const float4*)(half ? Wo : Wv);
        h2 = (__half2*)(half ? g_Woh : g_Wvh);
        int bid = (blockIdx.x - 2048) & 127;
        i0 = (size_t)bid * blockDim.x + threadIdx.x;
        stride = (size_t)128 * blockDim.x;
    }
    for (size_t i = i0; i < n4; i += stride) {
        float4 v = in4[i];
        __half2 a, b;
        a.x = __float2half(v.x); a.y = __float2half(v.y);
        b.x = __float2half(v.z); b.y = __float2half(v.w);
        h2[2*i] = a; h2[2*i+1] = b;
    }
}

// -------------------------------- GEMM -------------------------------------
// C[m,n] = sum_k A[m,k]*B[n,k], fp16 x fp16 -> fp32 acc. R6 core.
// which==0 additionally computes pass1's chunk partials in the epilogue
// (each warp's 32 accumulator rows are exactly one 32-t scan chunk).
#define TILEB 16384          // 128 rows x 128B
#define B_BASE 32768
#define GSMEM 65536
#define NCHUNK 16

__global__ void __launch_bounds__(256, 2)
k_gemm(int which, float* __restrict__ outC, const float* __restrict__ freqs) {
    extern __shared__ __align__(1024) char smem[];
    const __half *Ah, *Bh;
    if (which == 0) { Ah = g_Xh; Bh = g_Wvh; }
    else            { Ah = g_Rh; Bh = g_Woh; }

    const uint32_t sb = smem_to_u32(smem);
    const int tid = threadIdx.x, wid = tid >> 5, lid = tid & 31;
    const int warp_m = wid & 3, warp_n = wid >> 2;
    const int tn = blockIdx.x * 128, tm = blockIdx.y * 128;

    float acc[2][8][4];
    #pragma unroll
    for (int mi = 0; mi < 2; ++mi)
        #pragma unroll
        for (int ni = 0; ni < 8; ++ni)
            #pragma unroll
            for (int q = 0; q < 4; ++q) acc[mi][ni][q] = 0.f;

    auto load_chunk = [&](int c, int buf) {
        const int k0 = c << 6;
        const char* srcA = (const char*)(Ah + (size_t)tm * DD + k0);
        const char* srcB = (const char*)(Bh + (size_t)tn * DD + k0);
        const uint32_t dA = sb + buf * TILEB;
        const uint32_t dB = sb + B_BASE + buf * TILEB;
        #pragma unroll
        for (int i = 0; i < 4; ++i) {
            int j = tid + i * 256;
            int row = j >> 3, seg = j & 7;
            uint32_t off = SWZ((row << 7) | (seg << 4));
            size_t goff = (size_t)row * (DD * 2) + seg * 16;
            CP_ASYNC16(dA + off, srcA + goff);
            CP_ASYNC16(dB + off, srcB + goff);
        }
        CP_COMMIT();
    };

    load_chunk(0, 0);

    const int a_row = warp_m * 32 + (lid & 7) + ((lid >> 3) & 1) * 8;
    const int a_kof = ((lid >> 4) & 1) * 8;
    const int b_row = warp_n * 64 + (lid & 7) + ((lid >> 4) & 1) * 8;
    const int b_kof = ((lid >> 3) & 1) * 8;

    for (int c = 0; c < NCHUNK; ++c) {
        if (c + 1 < NCHUNK) { load_chunk(c + 1, (c + 1) & 1); CP_WAIT1(); }
        else                { CP_WAIT0(); }
        __syncthreads();

        const uint32_t aB = sb + (c & 1) * TILEB;
        const uint32_t bB = sb + B_BASE + (c & 1) * TILEB;
        #pragma unroll
        for (int kk = 0; kk < 4; ++kk) {
            uint32_t af[2][4], bf[8][2];
            #pragma unroll
            for (int mi = 0; mi < 2; ++mi) {
                uint32_t addr = aB + SWZ(((a_row + mi * 16) << 7) | ((a_kof + kk * 16) << 1));
                LDMX4(af[mi][0], af[mi][1], af[mi][2], af[mi][3], addr);
            }
            #pragma unroll
            for (int ni = 0; ni < 4; ++ni) {
                uint32_t r0, r1, r2, r3;
                uint32_t addr = bB + SWZ(((b_row + ni * 16) << 7) | ((b_kof + kk * 16) << 1));
                LDMX4(r0, r1, r2, r3, addr);
                bf[2*ni][0] = r0; bf[2*ni][1] = r1;
                bf[2*ni+1][0] = r2; bf[2*ni+1][1] = r3;
            }
            #pragma unroll
            for (int mi = 0; mi < 2; ++mi)
                #pragma unroll
                for (int ni = 0; ni < 8; ++ni)
                    MMA16816(acc[mi][ni], af[mi], bf[ni]);
        }
        __syncthreads();
    }

    if (which == 0) {
        // ---- V (fp16) stores ----
        #pragma unroll
        for (int mi = 0; mi < 2; ++mi) {
            int m = tm + warp_m * 32 + mi * 16 + (lid >> 2);
            int n0 = tn + warp_n * 64 + (lid & 3) * 2;
            __half* r0p = g_V + (size_t)m * DD + n0;
            __half* r1p = g_V + (size_t)(m + 8) * DD + n0;
            #pragma unroll
            for (int ni = 0; ni < 8; ++ni) {
                __half2 v0, v1;
                v0.x = __float2half(acc[mi][ni][0]); v0.y = __float2half(acc[mi][ni][1]);
                v1.x = __float2half(acc[mi][ni][2]); v1.y = __float2half(acc[mi][ni][3]);
                *(__half2*)(r0p + ni * 8) = v0;
                *(__half2*)(r1p + ni * 8) = v1;
            }
        }
        // ---- fused pass1: per-warp chunk partial ----
        const int b = tm >> 13;
        const int t_base = (tm & 8191) + warp_m * 32;
        const int ch = t_base >> 5;
        const int dbase = tn + warp_n * 64 + (lid & 3) * 2;
        #pragma unroll
        for (int nh = 0; nh < 2; ++nh) {
            float fr[8], pre[8], pim[8];
            #pragma unroll
            for (int nj = 0; nj < 4; ++nj) {
                int d = dbase + (nh * 4 + nj) * 8;
                fr[2*nj]   = freqs[d];
                fr[2*nj+1] = freqs[d + 1];
                pre[2*nj] = 0.f; pim[2*nj] = 0.f;
                pre[2*nj+1] = 0.f; pim[2*nj+1] = 0.f;
            }
            #pragma unroll
            for (int mi = 0; mi < 2; ++mi)
                #pragma unroll
                for (int h = 0; h < 2; ++h) {
                    float t_f = (float)(t_base + mi * 16 + (lid >> 2) + h * 8);
                    #pragma unroll
                    for (int nj = 0; nj < 4; ++nj) {
                        int ni = nh * 4 + nj;
                        #pragma unroll
                        for (int e = 0; e < 2; ++e) {
                            int j = 2 * nj + e;
                            float s, c; rot_sincos(t_f * fr[j], &s, &c);
                            float v = acc[mi][ni][h * 2 + e];
                            pre[j] += v * c; pim[j] += v * s;
                        }
                    }
                }
            #pragma unroll
            for (int j = 0; j < 8; ++j) {
                #pragma unroll
                for (int off = 4; off < 32; off <<= 1) {
                    pre[j] += __shfl_xor_sync(0xFFFFFFFFu, pre[j], off);
                    pim[j] += __shfl_xor_sync(0xFFFFFFFFu, pim[j], off);
                }
            }
            if (lid < 4) {
                #pragma unroll
                for (int nj = 0; nj < 4; ++nj) {
                    int d = dbase + (nh * 4 + nj) * 8;
                    float4 w = make_float4(pre[2*nj], pim[2*nj], pre[2*nj+1], pim[2*nj+1]);
                    *(float4*)&g_part[((size_t)b * PCH + ch) * DD + d] = w;
                }
            }
        }
    } else {
        #pragma unroll
        for (int mi = 0; mi < 2; ++mi) {
            int m = tm + warp_m * 32 + mi * 16 + (lid >> 2);
            int n0 = tn + warp_n * 64 + (lid & 3) * 2;
            float* r0p = outC + (size_t)m * DD + n0;
            float* r1p = outC + (size_t)(m + 8) * DD + n0;
            #pragma unroll
            for (int ni = 0; ni < 8; ++ni) {
                *(float2*)(r0p + ni * 8) = make_float2(acc[mi][ni][0], acc[mi][ni][1]);
                *(float2*)(r1p + ni * 8) = make_float2(acc[mi][ni][2], acc[mi][ni][3]);
            }
        }
    }
}

// ------------------------------- scan --------------------------------------
// pass2: one WARP per (b,d) scan of 256 chunk partials. Lane owns 8 chunks:
// load 8 (MLP=8), in-lane exclusive scan, shfl_up scan of lane totals.
__global__ void k_pass2() {
    int gw = (blockIdx.x * blockDim.x + threadIdx.x) >> 5;   // 0..2047
    int lid = threadIdx.x & 31;
    int b = gw >> 10, d = gw & 1023;
    size_t base = (size_t)b * PCH * DD + d;
    float2 v[8];
    #pragma unroll
    for (int u = 0; u < 8; ++u)
        v[u] = g_part[base + (size_t)(lid * 8 + u) * DD];
    float2 run = make_float2(0.f, 0.f);
    #pragma unroll
    for (int u = 0; u < 8; ++u) {
        float2 tv = v[u];
        v[u] = run;
        run.x += tv.x; run.y += tv.y;
    }
    float sx = run.x, sy = run.y;
    #pragma unroll
    for (int off = 1; off < 32; off <<= 1) {
        float tx = __shfl_up_sync(0xFFFFFFFFu, sx, off);
        float ty = __shfl_up_sync(0xFFFFFFFFu, sy, off);
        if (lid >= off) { sx += tx; sy += ty; }
    }
    float ox = sx - run.x, oy = sy - run.y;   // exclusive lane offset
    #pragma unroll
    for (int u = 0; u < 8; ++u)
        g_part[base + (size_t)(lid * 8 + u) * DD] = make_float2(v[u].x + ox, v[u].y + oy);
}

// pass3: finish scan within chunk, unbind, write R (fp16).
// Grid (PCH, 2): blockIdx.y selects d-half (0..511 / 512..1023); each thread
// owns ONE d-pair for BOTH batches (rotor shared). 512 blocks -> 2x occupancy
// vs the single-half version (fixes the 20.6%-occ latency bind seen in ncu).
__global__ void k_pass3(const float* __restrict__ freqs) {
    const int ch = blockIdx.x, tid = threadIdx.x;
    const int d = blockIdx.y * 512 + 2 * tid;
    float2 f = *(const float2*)(freqs + d);
    float2 a0[2], a1[2];
    *(float4*)&a0[0] = *(float4*)&g_part[(size_t)ch * DD + d];
    *(float4*)&a1[0] = *(float4*)&g_part[(size_t)(PCH + ch) * DD + d];

    size_t base = (size_t)ch * TCH * DD + d;
    const __half2* vp0 = (const __half2*)(g_V + base);
    const __half2* vp1 = (const __half2*)(g_V + base + (size_t)TT * DD);
    __half2* rh0 = (__half2*)(g_Rh + base);
    __half2* rh1 = (__half2*)(g_Rh + base + (size_t)TT * DD);
    for (int tl = 0; tl < TCH; ++tl) {
        float t = (float)(ch * TCH + tl);
        float sx, cx, sy, cy;
        rot_sincos(t * f.x, &sx, &cx);
        rot_sincos(t * f.y, &sy, &cy);
        float2 v0 = __half22float2(*vp0);
        float2 v1 = __half22float2(*vp1);
        a0[0].x += v0.x * cx; a0[0].y += v0.x * sx;
        a0[1].x += v0.y * cy; a0[1].y += v0.y * sy;
        a1[0].x += v1.x * cx; a1[0].y += v1.x * sx;
        a1[1].x += v1.y * cy; a1[1].y += v1.y * sy;
        __half2 r0, r1;
        r0.x = __float2half(a0[0].x * cx + a0[0].y * sx);
        r0.y = __float2half(a0[1].x * cy + a0[1].y * sy);
        r1.x = __float2half(a1[0].x * cx + a1[0].y * sx);
        r1.y = __float2half(a1[1].x * cy + a1[1].y * sy);
        *rh0 = r0;
        *rh1 = r1;
        vp0 += DD / 2; vp1 += DD / 2; rh0 += DD / 2; rh1 += DD / 2;
    }
}

// ------------------------------- launch ------------------------------------
extern "C" void kernel_launch(void* const* d_in, const int* in_sizes, int n_in,
                              void* d_out, int out_size) {
    const float* x     = (const float*)d_in[0];
    const float* Wv    = (const float*)d_in[2];
    const float* Wo    = (const float*)d_in[3];
    const float* freqs = (const float*)d_in[4];
    float* out = (float*)d_out;

    static int smem_set = 0;
    if (!smem_set) {
        cudaFuncSetAttribute(k_gemm, cudaFuncAttributeMaxDynamicSharedMemorySize, GSMEM);
        smem_set = 1;
    }

    k_split<<<2304, 256>>>(x, Wv, Wo);

    k_gemm<<<dim3(8, 128), 256, GSMEM>>>(0, nullptr, freqs);   // GEMM1 + fused pass1

    k_pass2<<<512, 128>>>();
    k_pass3<<<dim3(PCH, 2), 256>>>(freqs);

    k_gemm<<<dim3(8, 128), 256, GSMEM>>>(1, out, freqs);
}